// round 11
// baseline (speedup 1.0000x reference)
#include <cuda_runtime.h>

#define T_DIM 1024
#define O_DIM 512
#define D_DIM 256
#define H_DIM 512
#define M_DIM (T_DIM + O_DIM)   // 1536

// Scratch (no allocations allowed)
__device__ float g_A[M_DIM * H_DIM];   // rows 0..1023: ht ; rows 1024..1535: ho + b1
__device__ float g_u[M_DIM];           // g_A[m] . W2

typedef unsigned long long u64;

__device__ __forceinline__ u64 addx2(u64 a, u64 b) {
    u64 r; asm("add.rn.f32x2 %0,%1,%2;" : "=l"(r) : "l"(a), "l"(b)); return r;
}
__device__ __forceinline__ u64 fmax2(u64 a, u64 b, u64 c) {
    u64 r; asm("fma.rn.f32x2 %0,%1,%2,%3;" : "=l"(r) : "l"(a), "l"(b), "l"(c)); return r;
}

union F2U { float2 f; u64 u; };

__device__ __forceinline__ u64 pack2(float x, float y) {
    F2U t; t.f = make_float2(x, y); return t.u;
}

// ---------------------------------------------------------------------------
// Kernel 1: combined SGEMM (scalar FFMA).
//   m < 1024:  g_A[m][h] = sum_k z_t[m][k]   * W1[k][h]
//   m >= 1024: g_A[m][h] = sum_k z_o[m-T][k] * W1[256+k][h] + b1[h]
// Tiles: BM=32, BN=64, BK=16. 256 threads, 2(m) x 4(h) per thread.
// grid = 8 x 48 = 384 CTAs x 8 warps -> ~20.8 warps/SM resident.
// Zs rows padded to 34 floats (136B, mult of 8B -> LDS.64 aligned);
// Ws rows 68 floats (272B = 17*16B -> LDS.128 aligned).
// ---------------------------------------------------------------------------
__global__ __launch_bounds__(256) void gemm_kernel(
    const float* __restrict__ z_t, const float* __restrict__ z_o,
    const float* __restrict__ W1,  const float* __restrict__ b1)
{
    __shared__ __align__(16) float Zs[16][34];   // [k][m]
    __shared__ __align__(16) float Ws[16][68];   // [k][h]

    const int tid = threadIdx.x;
    const int tx = tid & 15;         // h: tx*4
    const int ty = tid >> 4;         // m: ty*2 + i (0..15 -> 32 rows)
    const int m0 = blockIdx.y * 32;
    const int h0 = blockIdx.x * 64;
    const bool is_o = (m0 >= T_DIM);
    const float* Z = is_o ? z_o : z_t;
    const int mrow0 = is_o ? (m0 - T_DIM) : m0;
    const int kbase = is_o ? D_DIM : 0;

    // staging mapping
    const int zm  = tid & 31;        // 0..31 (m)
    const int zkp = (tid >> 5) * 2;  // k pair: 0,2,...,14
    const int wk  = tid >> 4;        // 0..15
    const int wh  = (tid & 15) * 4;  // 0..60

    const float* zp = Z + (mrow0 + zm) * D_DIM + zkp;
    const float* wp = W1 + (kbase + wk) * H_DIM + h0 + wh;

    float acc[2][4] = {};

    float2 zr = *(const float2*)zp;
    float4 wr = *(const float4*)wp;

    for (int c = 0; c < 16; ++c) {
        Zs[zkp + 0][zm] = zr.x;
        Zs[zkp + 1][zm] = zr.y;
        *(float4*)&Ws[wk][wh] = wr;
        __syncthreads();
        if (c < 15) {
            zr = *(const float2*)(zp + (c + 1) * 16);
            wr = *(const float4*)(wp + (c + 1) * 16 * H_DIM);
        }
        #pragma unroll
        for (int k = 0; k < 16; ++k) {
            float2 a = *(const float2*)&Zs[k][ty * 2];
            float4 b = *(const float4*)&Ws[k][tx * 4];
            float bv[4] = {b.x, b.y, b.z, b.w};
            #pragma unroll
            for (int j = 0; j < 4; ++j) {
                acc[0][j] = fmaf(a.x, bv[j], acc[0][j]);
                acc[1][j] = fmaf(a.y, bv[j], acc[1][j]);
            }
        }
        __syncthreads();
    }

    float bj[4] = {0.f, 0.f, 0.f, 0.f};
    if (is_o) {
        #pragma unroll
        for (int j = 0; j < 4; ++j) bj[j] = b1[h0 + tx * 4 + j];
    }
    #pragma unroll
    for (int i = 0; i < 2; ++i) {
        float4 v = make_float4(acc[i][0] + bj[0], acc[i][1] + bj[1],
                               acc[i][2] + bj[2], acc[i][3] + bj[3]);
        *(float4*)&g_A[(m0 + ty * 2 + i) * H_DIM + h0 + tx * 4] = v;
    }
}

// ---------------------------------------------------------------------------
// Kernel 2: g_u[m] = g_A[m] . W2   (one warp per row)
// ---------------------------------------------------------------------------
__global__ __launch_bounds__(256) void rowdot_kernel(const float* __restrict__ W2)
{
    const int warp = blockIdx.x * 8 + (threadIdx.x >> 5);
    const int lane = threadIdx.x & 31;
    const float* row = g_A + warp * H_DIM;
    float s = 0.f;
    #pragma unroll
    for (int q = 0; q < 4; ++q) {
        const int idx = q * 128 + lane * 4;
        float4 a = *(const float4*)(row + idx);
        float4 w = *(const float4*)(W2 + idx);
        s += a.x * w.x + a.y * w.y + a.z * w.z + a.w * w.w;
    }
    #pragma unroll
    for (int d = 16; d >= 1; d >>= 1) s += __shfl_xor_sync(0xFFFFFFFFu, s, d);
    if (lane == 0) g_u[warp] = s;
}

// ---------------------------------------------------------------------------
// Kernel 3: main abs-bilinear loop.
// out[t][o] = 0.505*(u[t]+u[T+o]) + 0.495 * sum_h |A[t][h]+A[T+o][h]| * w[h] + b2
// Tile 32(t) x 64(o), 256 threads, 2(t) x 4(o) per thread (o strided tx+16r),
// h packed by 2 (f32x2), chunks of 16 h-pairs. grid = 8 x 32 = 256 CTAs
// x 8 warps -> ~13.8 warps/SM. Smem stride 17 u64 keeps the hot B read
// (Bs[tx+16r][k]) on 16 distinct banks; A reads are 4-row broadcasts.
// ---------------------------------------------------------------------------
__global__ __launch_bounds__(256) void cfm_main_kernel(
    const float* __restrict__ W2, const float* __restrict__ b2,
    float* __restrict__ out)
{
    __shared__ __align__(16) u64 As[32][17];   // [t-row][h-pair]
    __shared__ __align__(16) u64 Bs[64][17];   // [o-row][h-pair]
    __shared__ u64 wsm[16];

    const int tid = threadIdx.x;
    const int tx = tid & 15;         // o: cols tx + 16r
    const int ty = tid >> 4;         // t: rows ty*2 + i  (0..15 -> 32 rows)
    const int t0 = blockIdx.y * 32;
    const int o0 = blockIdx.x * 64;

    // staging mapping (per 16-pair chunk = 32 floats per row)
    const int arow = tid >> 3;           // 0..31
    const int apg  = (tid & 7) * 2;      // u64 cols 0,2,...,14 (4 floats)
    const int brow = tid >> 2;           // 0..63
    const int bpg  = (tid & 3) * 4;      // u64 cols 0,4,8,12   (8 floats)
    const float* Ap = g_A + (t0 + arow) * H_DIM + apg * 2;
    const float* Bp = g_A + (T_DIM + o0 + brow) * H_DIM + bpg * 2;

    u64 acc[2][4] = {};

    float4 ra, rb[2];
    ra = *(const float4*)Ap;
    rb[0] = *(const float4*)(Bp + 0);
    rb[1] = *(const float4*)(Bp + 4);
    float2 wf = make_float2(0.f, 0.f);
    if (tid < 16) wf = *(const float2*)(W2 + tid * 2);

    const u64 ABSM = 0x7FFFFFFF7FFFFFFFULL;

    for (int c = 0; c < 16; ++c) {
        As[arow][apg + 0] = pack2(ra.x, ra.y);
        As[arow][apg + 1] = pack2(ra.z, ra.w);
        Bs[brow][bpg + 0] = pack2(rb[0].x, rb[0].y);
        Bs[brow][bpg + 1] = pack2(rb[0].z, rb[0].w);
        Bs[brow][bpg + 2] = pack2(rb[1].x, rb[1].y);
        Bs[brow][bpg + 3] = pack2(rb[1].z, rb[1].w);
        if (tid < 16) wsm[tid] = pack2(wf.x, wf.y);
        __syncthreads();
        if (c < 15) {
            const int off = (c + 1) * 32;   // 32 floats = 16 pairs per chunk
            ra = *(const float4*)(Ap + off);
            rb[0] = *(const float4*)(Bp + off + 0);
            rb[1] = *(const float4*)(Bp + off + 4);
            if (tid < 16) wf = *(const float2*)(W2 + (c + 1) * 32 + tid * 2);
        }
        #pragma unroll 8
        for (int k = 0; k < 16; ++k) {
            u64 a2[2], bv[4];
            a2[0] = As[ty * 2 + 0][k];
            a2[1] = As[ty * 2 + 1][k];
            #pragma unroll
            for (int r = 0; r < 4; ++r) bv[r] = Bs[tx + 16 * r][k];
            const u64 w2 = wsm[k];
            #pragma unroll
            for (int i = 0; i < 2; ++i)
                #pragma unroll
                for (int j = 0; j < 4; ++j) {
                    u64 s = addx2(a2[i], bv[j]);
                    s &= ABSM;                       // |.| both lanes (2x LOP3, alu pipe)
                    acc[i][j] = fmax2(s, w2, acc[i][j]);
                }
        }
        __syncthreads();
    }

    // epilogue (thread's columns are o0 + tx + 16r, rows t0 + ty*2 + i)
    const float b2v = b2[0];
    float ut[2], uo[4];
    #pragma unroll
    for (int i = 0; i < 2; ++i) ut[i] = g_u[t0 + ty * 2 + i];
    #pragma unroll
    for (int r = 0; r < 4; ++r) uo[r] = g_u[T_DIM + o0 + tx + 16 * r];

    #pragma unroll
    for (int i = 0; i < 2; ++i) {
        float* orow = out + (t0 + ty * 2 + i) * O_DIM + o0;
        #pragma unroll
        for (int r = 0; r < 4; ++r) {
            F2U cu; cu.u = acc[i][r];
            const float S = cu.f.x + cu.f.y;
            orow[tx + 16 * r] = 0.505f * (ut[i] + uo[r]) + 0.495f * S + b2v;
        }
    }
}

// ---------------------------------------------------------------------------
extern "C" void kernel_launch(void* const* d_in, const int* in_sizes, int n_in,
                              void* d_out, int out_size)
{
    const float* z_t = (const float*)d_in[0];   // [1024,256]
    const float* z_o = (const float*)d_in[1];   // [512,256]
    const float* W1  = (const float*)d_in[2];   // [512,512]
    const float* b1  = (const float*)d_in[3];   // [512]
    const float* W2  = (const float*)d_in[4];   // [512,1]
    const float* b2  = (const float*)d_in[5];   // [1]
    float* out = (float*)d_out;                 // [1024,512]

    (void)in_sizes; (void)n_in; (void)out_size;

    gemm_kernel<<<dim3(H_DIM / 64, M_DIM / 32), 256>>>(z_t, z_o, W1, b1);
    rowdot_kernel<<<M_DIM / 8, 256>>>(W2);
    cfm_main_kernel<<<dim3(O_DIM / 64, T_DIM / 32), 256>>>(W2, b2, out);
}

// round 13
// speedup vs baseline: 1.1725x; 1.1725x over previous
#include <cuda_runtime.h>

#define T_DIM 1024
#define O_DIM 512
#define D_DIM 256
#define H_DIM 512
#define M_DIM (T_DIM + O_DIM)   // 1536

// Scratch (no allocations allowed)
__device__ float g_A[M_DIM * H_DIM];       // rows 0..1023: ht ; 1024..1535: ho + b1
__device__ float g_u[M_DIM];               // g_A[m] . W2
__device__ float g_S[2 * T_DIM * O_DIM];   // split-h partial |.|-sums

typedef unsigned long long u64;

__device__ __forceinline__ u64 addx2(u64 a, u64 b) {
    u64 r; asm("add.rn.f32x2 %0,%1,%2;" : "=l"(r) : "l"(a), "l"(b)); return r;
}
__device__ __forceinline__ u64 fmax2(u64 a, u64 b, u64 c) {
    u64 r; asm("fma.rn.f32x2 %0,%1,%2,%3;" : "=l"(r) : "l"(a), "l"(b), "l"(c)); return r;
}

union F2U { float2 f; u64 u; };

__device__ __forceinline__ u64 pack2(float x, float y) {
    F2U t; t.f = make_float2(x, y); return t.u;
}

// ---------------------------------------------------------------------------
// Kernel 1: combined SGEMM (R10 config — proven 18.8us).
// Tiles: BM=32, BN=64, BK=16. 128 threads, 4x4 per thread. grid = 8x48 = 384.
// ---------------------------------------------------------------------------
__global__ __launch_bounds__(128) void gemm_kernel(
    const float* __restrict__ z_t, const float* __restrict__ z_o,
    const float* __restrict__ W1,  const float* __restrict__ b1)
{
    __shared__ __align__(16) float Zs[16][36];   // [k][m], 144B rows (16B-aligned)
    __shared__ __align__(16) float Ws[16][68];   // [k][h], 272B rows (16B-aligned)

    const int tid = threadIdx.x;
    const int tx = tid & 15;         // h: tx*4
    const int ty = tid >> 4;         // m: ty*4 (0..7 -> 32 rows)
    const int m0 = blockIdx.y * 32;
    const int h0 = blockIdx.x * 64;
    const bool is_o = (m0 >= T_DIM);
    const float* Z = is_o ? z_o : z_t;
    const int mrow0 = is_o ? (m0 - T_DIM) : m0;
    const int kbase = is_o ? D_DIM : 0;

    const int zm = tid >> 2;         // 0..31
    const int zk = (tid & 3) * 4;    // 0,4,8,12
    const int wk = tid >> 3;         // 0..15
    const int wh = (tid & 7) * 8;    // 0..56

    const float* zp = Z + (mrow0 + zm) * D_DIM + zk;
    const float* wp = W1 + (kbase + wk) * H_DIM + h0 + wh;

    float acc[4][4] = {};

    float4 zr = *(const float4*)zp;
    float4 wr0 = *(const float4*)wp;
    float4 wr1 = *(const float4*)(wp + 4);

    for (int c = 0; c < 16; ++c) {
        Zs[zk + 0][zm] = zr.x; Zs[zk + 1][zm] = zr.y;
        Zs[zk + 2][zm] = zr.z; Zs[zk + 3][zm] = zr.w;
        *(float4*)&Ws[wk][wh]     = wr0;
        *(float4*)&Ws[wk][wh + 4] = wr1;
        __syncthreads();
        if (c < 15) {
            zr  = *(const float4*)(zp + (c + 1) * 16);
            wr0 = *(const float4*)(wp + (c + 1) * 16 * H_DIM);
            wr1 = *(const float4*)(wp + (c + 1) * 16 * H_DIM + 4);
        }
        #pragma unroll
        for (int k = 0; k < 16; ++k) {
            float4 a = *(const float4*)&Zs[k][ty * 4];
            float4 b = *(const float4*)&Ws[k][tx * 4];
            float av[4] = {a.x, a.y, a.z, a.w};
            float bv[4] = {b.x, b.y, b.z, b.w};
            #pragma unroll
            for (int i = 0; i < 4; ++i)
                #pragma unroll
                for (int j = 0; j < 4; ++j)
                    acc[i][j] = fmaf(av[i], bv[j], acc[i][j]);
        }
        __syncthreads();
    }

    float bj[4] = {0.f, 0.f, 0.f, 0.f};
    if (is_o) {
        #pragma unroll
        for (int j = 0; j < 4; ++j) bj[j] = b1[h0 + tx * 4 + j];
    }
    #pragma unroll
    for (int i = 0; i < 4; ++i) {
        float4 v = make_float4(acc[i][0] + bj[0], acc[i][1] + bj[1],
                               acc[i][2] + bj[2], acc[i][3] + bj[3]);
        *(float4*)&g_A[(m0 + ty * 4 + i) * H_DIM + h0 + tx * 4] = v;
    }
}

// ---------------------------------------------------------------------------
// Kernel 2: g_u[m] = g_A[m] . W2   (one warp per row)
// ---------------------------------------------------------------------------
__global__ __launch_bounds__(256) void rowdot_kernel(const float* __restrict__ W2)
{
    const int warp = blockIdx.x * 8 + (threadIdx.x >> 5);
    const int lane = threadIdx.x & 31;
    const float* row = g_A + warp * H_DIM;
    float s = 0.f;
    #pragma unroll
    for (int q = 0; q < 4; ++q) {
        const int idx = q * 128 + lane * 4;
        float4 a = *(const float4*)(row + idx);
        float4 w = *(const float4*)(W2 + idx);
        s += a.x * w.x + a.y * w.y + a.z * w.z + a.w * w.w;
    }
    #pragma unroll
    for (int d = 16; d >= 1; d >>= 1) s += __shfl_xor_sync(0xFFFFFFFFu, s, d);
    if (lane == 0) g_u[warp] = s;
}

// ---------------------------------------------------------------------------
// Kernel 3: abs-bilinear PARTIAL sums, h split 2 ways (blockIdx.z).
// g_S[z][t][o] = sum_{h in half z} |A[t][h]+A[T+o][h]| * w[h]
// Tile 32(t) x 64(o), 128 threads, 4x4 per thread (o strided tx+16r),
// f32x2 packed, 8 chunks of 16 h-pairs per CTA. grid = 8 x 32 x 2 = 512 CTAs
// -> ~13.8 warps/SM (vs 6.9 before). Same conflict-free stride-17 layout.
// ---------------------------------------------------------------------------
__global__ __launch_bounds__(128) void cfm_partial_kernel(const float* __restrict__ W2)
{
    __shared__ __align__(16) u64 As[32][17];   // [t-row][h-pair]
    __shared__ __align__(16) u64 Bs[64][17];   // [o-row][h-pair]
    __shared__ u64 wsm[16];

    const int tid = threadIdx.x;
    const int tx = tid & 15;         // o: cols tx + 16r
    const int ty = tid >> 4;         // t: rows ty*4 + i  (0..7 -> 32 rows)
    const int t0 = blockIdx.y * 32;
    const int o0 = blockIdx.x * 64;
    const int hbase = blockIdx.z * 256;        // h offset of this split (floats)

    // staging mapping (per 16-pair chunk = 32 floats per row)
    const int arow = tid >> 2;           // 0..31
    const int apg  = (tid & 3) * 4;      // u64 cols 0,4,8,12 (8 floats)
    const int brow = tid >> 1;           // 0..63
    const int bpg  = (tid & 1) * 8;      // u64 cols 0,8      (16 floats)
    const float* Ap = g_A + (t0 + arow) * H_DIM + hbase + apg * 2;
    const float* Bp = g_A + (T_DIM + o0 + brow) * H_DIM + hbase + bpg * 2;

    u64 acc[4][4] = {};

    float4 ra[2], rb[4];
    ra[0] = *(const float4*)(Ap + 0);
    ra[1] = *(const float4*)(Ap + 4);
    #pragma unroll
    for (int r = 0; r < 4; ++r) rb[r] = *(const float4*)(Bp + r * 4);
    float2 wf = make_float2(0.f, 0.f);
    if (tid < 16) wf = *(const float2*)(W2 + hbase + tid * 2);

    const u64 ABSM = 0x7FFFFFFF7FFFFFFFULL;

    for (int c = 0; c < 8; ++c) {
        As[arow][apg + 0] = pack2(ra[0].x, ra[0].y);
        As[arow][apg + 1] = pack2(ra[0].z, ra[0].w);
        As[arow][apg + 2] = pack2(ra[1].x, ra[1].y);
        As[arow][apg + 3] = pack2(ra[1].z, ra[1].w);
        #pragma unroll
        for (int r = 0; r < 4; ++r) {
            Bs[brow][bpg + r * 2 + 0] = pack2(rb[r].x, rb[r].y);
            Bs[brow][bpg + r * 2 + 1] = pack2(rb[r].z, rb[r].w);
        }
        if (tid < 16) wsm[tid] = pack2(wf.x, wf.y);
        __syncthreads();
        if (c < 7) {
            const int off = (c + 1) * 32;   // 32 floats = 16 pairs per chunk
            ra[0] = *(const float4*)(Ap + off + 0);
            ra[1] = *(const float4*)(Ap + off + 4);
            #pragma unroll
            for (int r = 0; r < 4; ++r) rb[r] = *(const float4*)(Bp + off + r * 4);
            if (tid < 16) wf = *(const float2*)(W2 + hbase + (c + 1) * 32 + tid * 2);
        }
        #pragma unroll 8
        for (int k = 0; k < 16; ++k) {
            u64 a2[4], bv[4];
            #pragma unroll
            for (int i = 0; i < 4; ++i) a2[i] = As[ty * 4 + i][k];
            #pragma unroll
            for (int r = 0; r < 4; ++r) bv[r] = Bs[tx + 16 * r][k];
            const u64 w2 = wsm[k];
            #pragma unroll
            for (int i = 0; i < 4; ++i)
                #pragma unroll
                for (int j = 0; j < 4; ++j) {
                    u64 s = addx2(a2[i], bv[j]);
                    s &= ABSM;                       // |.| both lanes (2x LOP3, alu pipe)
                    acc[i][j] = fmax2(s, w2, acc[i][j]);
                }
        }
        __syncthreads();
    }

    // write raw partial sums (no scaling here)
    float* Sp = g_S + blockIdx.z * (T_DIM * O_DIM);
    #pragma unroll
    for (int i = 0; i < 4; ++i) {
        float* srow = Sp + (t0 + ty * 4 + i) * O_DIM + o0;
        #pragma unroll
        for (int r = 0; r < 4; ++r) {
            F2U cu; cu.u = acc[i][r];
            srow[tx + 16 * r] = cu.f.x + cu.f.y;
        }
    }
}

// ---------------------------------------------------------------------------
// Kernel 4: combine partials + rank-1 linear part + bias.
// out[t][o] = 0.505*(u[t]+u[T+o]) + 0.495*(S0+S1) + b2
// ---------------------------------------------------------------------------
__global__ __launch_bounds__(256) void combine_kernel(
    const float* __restrict__ b2, float* __restrict__ out)
{
    const int idx4 = (blockIdx.x * 256 + threadIdx.x) * 4;   // over T*O
    const int t = idx4 >> 9;          // /512
    const int o = idx4 & 511;
    float4 s0 = *(const float4*)&g_S[idx4];
    float4 s1 = *(const float4*)&g_S[T_DIM * O_DIM + idx4];
    float4 uo = *(const float4*)&g_u[T_DIM + o];
    const float ut = g_u[t];
    const float bb = b2[0];
    float4 v;
    v.x = 0.505f * (ut + uo.x) + 0.495f * (s0.x + s1.x) + bb;
    v.y = 0.505f * (ut + uo.y) + 0.495f * (s0.y + s1.y) + bb;
    v.z = 0.505f * (ut + uo.z) + 0.495f * (s0.z + s1.z) + bb;
    v.w = 0.505f * (ut + uo.w) + 0.495f * (s0.w + s1.w) + bb;
    *(float4*)&out[idx4] = v;
}

// ---------------------------------------------------------------------------
extern "C" void kernel_launch(void* const* d_in, const int* in_sizes, int n_in,
                              void* d_out, int out_size)
{
    const float* z_t = (const float*)d_in[0];   // [1024,256]
    const float* z_o = (const float*)d_in[1];   // [512,256]
    const float* W1  = (const float*)d_in[2];   // [512,512]
    const float* b1  = (const float*)d_in[3];   // [512]
    const float* W2  = (const float*)d_in[4];   // [512,1]
    const float* b2  = (const float*)d_in[5];   // [1]
    float* out = (float*)d_out;                 // [1024,512]

    (void)in_sizes; (void)n_in; (void)out_size;

    gemm_kernel<<<dim3(H_DIM / 64, M_DIM / 32), 128>>>(z_t, z_o, W1, b1);
    rowdot_kernel<<<M_DIM / 8, 256>>>(W2);
    cfm_partial_kernel<<<dim3(O_DIM / 64, T_DIM / 32, 2), 128>>>(W2);
    combine_kernel<<<(T_DIM * O_DIM) / (256 * 4), 256>>>(b2, out);
}

// round 15
// speedup vs baseline: 1.3092x; 1.1166x over previous
#include <cuda_runtime.h>
#include <cstdint>

#define T_DIM 1024
#define O_DIM 512
#define D_DIM 256
#define H_DIM 512
#define M_DIM (T_DIM + O_DIM)   // 1536

// Scratch (no allocations allowed)
__device__ float g_A[M_DIM * H_DIM];   // rows 0..1023: ht ; 1024..1535: ho + b1
__device__ float g_u[M_DIM];           // g_A[m] . W2

typedef unsigned long long u64;

__device__ __forceinline__ u64 addx2(u64 a, u64 b) {
    u64 r; asm("add.rn.f32x2 %0,%1,%2;" : "=l"(r) : "l"(a), "l"(b)); return r;
}
__device__ __forceinline__ u64 fmax2(u64 a, u64 b, u64 c) {
    u64 r; asm("fma.rn.f32x2 %0,%1,%2,%3;" : "=l"(r) : "l"(a), "l"(b), "l"(c)); return r;
}

union F2U { float2 f; u64 u; };

__device__ __forceinline__ u64 pack2(float x, float y) {
    F2U t; t.f = make_float2(x, y); return t.u;
}

__device__ __forceinline__ float to_tf32(float x) {
    uint32_t r; asm("cvt.rna.tf32.f32 %0, %1;" : "=r"(r) : "f"(x));
    return __uint_as_float(r);
}

__device__ __forceinline__ void mma_tf32(float* d,
                                         const uint32_t* a, const uint32_t* b,
                                         const float* c) {
    asm volatile(
        "mma.sync.aligned.m16n8k8.row.col.f32.tf32.tf32.f32 "
        "{%0,%1,%2,%3}, {%4,%5,%6,%7}, {%8,%9}, {%10,%11,%12,%13};"
        : "=f"(d[0]), "=f"(d[1]), "=f"(d[2]), "=f"(d[3])
        : "r"(a[0]), "r"(a[1]), "r"(a[2]), "r"(a[3]),
          "r"(b[0]), "r"(b[1]),
          "f"(c[0]), "f"(c[1]), "f"(c[2]), "f"(c[3]));
}

// ---------------------------------------------------------------------------
// Kernel 1: combined GEMM via tf32 mma.sync (m16n8k8).
//   m < 1024:  g_A[m][h] = sum_k z_t[m][k]   * W1[k][h]
//   m >= 1024: g_A[m][h] = sum_k z_o[m-T][k] * W1[256+k][h] + b1[h]
// Tiles: BM=32, BN=64, BK=16. 128 threads = 4 warps, each warp owns a
// 32(m) x 16(n) slab = 2x2 m16n8k8 tiles. grid = 8 x 48 = 384 CTAs.
// Smem strides: Zs stride 40, Ws stride 72 -> fragment LDS addr mod 32
// = 8k + row: 32 distinct banks, conflict-free.
// ---------------------------------------------------------------------------
__global__ __launch_bounds__(128) void gemm_kernel(
    const float* __restrict__ z_t, const float* __restrict__ z_o,
    const float* __restrict__ W1,  const float* __restrict__ b1)
{
    __shared__ __align__(16) float Zs[16][40];   // [k][m]
    __shared__ __align__(16) float Ws[16][72];   // [k][n]

    const int tid  = threadIdx.x;
    const int warp = tid >> 5;
    const int lane = tid & 31;
    const int q = lane >> 2;          // group id 0..7
    const int r = lane & 3;           // thread-in-group 0..3
    const int nw = warp * 16;         // warp n offset

    const int m0 = blockIdx.y * 32;
    const int h0 = blockIdx.x * 64;
    const bool is_o = (m0 >= T_DIM);
    const float* Z = is_o ? z_o : z_t;
    const int mrow0 = is_o ? (m0 - T_DIM) : m0;
    const int kbase = is_o ? D_DIM : 0;

    // staging mapping
    const int zm = tid >> 2;          // 0..31
    const int zk = (tid & 3) * 4;     // 0,4,8,12
    const int wk = tid >> 3;          // 0..15
    const int wh = (tid & 7) * 8;     // 0..56

    const float* zp = Z + (mrow0 + zm) * D_DIM + zk;
    const float* wp = W1 + (kbase + wk) * H_DIM + h0 + wh;

    float acc[2][2][4] = {};

    float4 zr  = *(const float4*)zp;
    float4 wr0 = *(const float4*)wp;
    float4 wr1 = *(const float4*)(wp + 4);
    zr.x = to_tf32(zr.x); zr.y = to_tf32(zr.y);
    zr.z = to_tf32(zr.z); zr.w = to_tf32(zr.w);
    wr0.x = to_tf32(wr0.x); wr0.y = to_tf32(wr0.y);
    wr0.z = to_tf32(wr0.z); wr0.w = to_tf32(wr0.w);
    wr1.x = to_tf32(wr1.x); wr1.y = to_tf32(wr1.y);
    wr1.z = to_tf32(wr1.z); wr1.w = to_tf32(wr1.w);

    for (int c = 0; c < 16; ++c) {
        Zs[zk + 0][zm] = zr.x; Zs[zk + 1][zm] = zr.y;
        Zs[zk + 2][zm] = zr.z; Zs[zk + 3][zm] = zr.w;
        *(float4*)&Ws[wk][wh]     = wr0;
        *(float4*)&Ws[wk][wh + 4] = wr1;
        __syncthreads();
        if (c < 15) {
            zr  = *(const float4*)(zp + (c + 1) * 16);
            wr0 = *(const float4*)(wp + (c + 1) * 16 * H_DIM);
            wr1 = *(const float4*)(wp + (c + 1) * 16 * H_DIM + 4);
            zr.x = to_tf32(zr.x); zr.y = to_tf32(zr.y);
            zr.z = to_tf32(zr.z); zr.w = to_tf32(zr.w);
            wr0.x = to_tf32(wr0.x); wr0.y = to_tf32(wr0.y);
            wr0.z = to_tf32(wr0.z); wr0.w = to_tf32(wr0.w);
            wr1.x = to_tf32(wr1.x); wr1.y = to_tf32(wr1.y);
            wr1.z = to_tf32(wr1.z); wr1.w = to_tf32(wr1.w);
        }
        #pragma unroll
        for (int ks = 0; ks < 2; ++ks) {
            const int k0 = ks * 8;
            uint32_t a[2][4], b[2][2];
            #pragma unroll
            for (int i = 0; i < 2; ++i) {
                a[i][0] = __float_as_uint(Zs[k0 + r    ][16 * i + q    ]);
                a[i][1] = __float_as_uint(Zs[k0 + r    ][16 * i + q + 8]);
                a[i][2] = __float_as_uint(Zs[k0 + r + 4][16 * i + q    ]);
                a[i][3] = __float_as_uint(Zs[k0 + r + 4][16 * i + q + 8]);
            }
            #pragma unroll
            for (int j = 0; j < 2; ++j) {
                b[j][0] = __float_as_uint(Ws[k0 + r    ][nw + 8 * j + q]);
                b[j][1] = __float_as_uint(Ws[k0 + r + 4][nw + 8 * j + q]);
            }
            #pragma unroll
            for (int i = 0; i < 2; ++i)
                #pragma unroll
                for (int j = 0; j < 2; ++j)
                    mma_tf32(acc[i][j], a[i], b[j], acc[i][j]);
        }
        __syncthreads();
    }

    // epilogue: c0:(q, r*2) c1:(q, r*2+1) c2:(q+8, r*2) c3:(q+8, r*2+1)
    #pragma unroll
    for (int i = 0; i < 2; ++i) {
        #pragma unroll
        for (int j = 0; j < 2; ++j) {
            const int ncol = h0 + nw + 8 * j + r * 2;
            float bx = 0.f, by = 0.f;
            if (is_o) { bx = b1[ncol]; by = b1[ncol + 1]; }
            const int mr0 = m0 + 16 * i + q;
            *(float2*)&g_A[mr0 * H_DIM + ncol] =
                make_float2(acc[i][j][0] + bx, acc[i][j][1] + by);
            *(float2*)&g_A[(mr0 + 8) * H_DIM + ncol] =
                make_float2(acc[i][j][2] + bx, acc[i][j][3] + by);
        }
    }
}

// ---------------------------------------------------------------------------
// Kernel 2: g_u[m] = g_A[m] . W2   (one warp per row)
// ---------------------------------------------------------------------------
__global__ __launch_bounds__(256) void rowdot_kernel(const float* __restrict__ W2)
{
    const int warp = blockIdx.x * 8 + (threadIdx.x >> 5);
    const int lane = threadIdx.x & 31;
    const float* row = g_A + warp * H_DIM;
    float s = 0.f;
    #pragma unroll
    for (int q = 0; q < 4; ++q) {
        const int idx = q * 128 + lane * 4;
        float4 a = *(const float4*)(row + idx);
        float4 w = *(const float4*)(W2 + idx);
        s += a.x * w.x + a.y * w.y + a.z * w.z + a.w * w.w;
    }
    #pragma unroll
    for (int d = 16; d >= 1; d >>= 1) s += __shfl_xor_sync(0xFFFFFFFFu, s, d);
    if (lane == 0) g_u[warp] = s;
}

// ---------------------------------------------------------------------------
// Kernel 3: main abs-bilinear loop (R10 config — proven fastest).
// out[t][o] = 0.505*(u[t]+u[T+o]) + 0.495 * sum_h |A[t][h]+A[T+o][h]| * w[h] + b2
// Tile 32(t) x 64(o), 128 threads, 4x4 per thread (o strided tx+16r),
// f32x2 packed, 16 chunks of 16 h-pairs. grid = 8 x 32 = 256 CTAs.
// ---------------------------------------------------------------------------
__global__ __launch_bounds__(128) void cfm_main_kernel(
    const float* __restrict__ W2, const float* __restrict__ b2,
    float* __restrict__ out)
{
    __shared__ __align__(16) u64 As[32][17];   // [t-row][h-pair]
    __shared__ __align__(16) u64 Bs[64][17];   // [o-row][h-pair]
    __shared__ u64 wsm[16];

    const int tid = threadIdx.x;
    const int tx = tid & 15;         // o: cols tx + 16r
    const int ty = tid >> 4;         // t: rows ty*4 + i  (0..7 -> 32 rows)
    const int t0 = blockIdx.y * 32;
    const int o0 = blockIdx.x * 64;

    const int arow = tid >> 2;           // 0..31
    const int apg  = (tid & 3) * 4;      // u64 cols 0,4,8,12 (8 floats)
    const int brow = tid >> 1;           // 0..63
    const int bpg  = (tid & 1) * 8;      // u64 cols 0,8      (16 floats)
    const float* Ap = g_A + (t0 + arow) * H_DIM + apg * 2;
    const float* Bp = g_A + (T_DIM + o0 + brow) * H_DIM + bpg * 2;

    u64 acc[4][4] = {};

    float4 ra[2], rb[4];
    ra[0] = *(const float4*)(Ap + 0);
    ra[1] = *(const float4*)(Ap + 4);
    #pragma unroll
    for (int r = 0; r < 4; ++r) rb[r] = *(const float4*)(Bp + r * 4);
    float2 wf = make_float2(0.f, 0.f);
    if (tid < 16) wf = *(const float2*)(W2 + tid * 2);

    const u64 ABSM = 0x7FFFFFFF7FFFFFFFULL;

    for (int c = 0; c < 16; ++c) {
        As[arow][apg + 0] = pack2(ra[0].x, ra[0].y);
        As[arow][apg + 1] = pack2(ra[0].z, ra[0].w);
        As[arow][apg + 2] = pack2(ra[1].x, ra[1].y);
        As[arow][apg + 3] = pack2(ra[1].z, ra[1].w);
        #pragma unroll
        for (int r = 0; r < 4; ++r) {
            Bs[brow][bpg + r * 2 + 0] = pack2(rb[r].x, rb[r].y);
            Bs[brow][bpg + r * 2 + 1] = pack2(rb[r].z, rb[r].w);
        }
        if (tid < 16) wsm[tid] = pack2(wf.x, wf.y);
        __syncthreads();
        if (c < 15) {
            const int off = (c + 1) * 32;   // 32 floats = 16 pairs per chunk
            ra[0] = *(const float4*)(Ap + off + 0);
            ra[1] = *(const float4*)(Ap + off + 4);
            #pragma unroll
            for (int r = 0; r < 4; ++r) rb[r] = *(const float4*)(Bp + off + r * 4);
            if (tid < 16) wf = *(const float2*)(W2 + (c + 1) * 32 + tid * 2);
        }
        #pragma unroll 8
        for (int k = 0; k < 16; ++k) {
            u64 a2[4], bv[4];
            #pragma unroll
            for (int i = 0; i < 4; ++i) a2[i] = As[ty * 4 + i][k];
            #pragma unroll
            for (int r = 0; r < 4; ++r) bv[r] = Bs[tx + 16 * r][k];
            const u64 w2 = wsm[k];
            #pragma unroll
            for (int i = 0; i < 4; ++i)
                #pragma unroll
                for (int j = 0; j < 4; ++j) {
                    u64 s = addx2(a2[i], bv[j]);
                    s &= ABSM;                       // |.| both lanes (2x LOP3, alu pipe)
                    acc[i][j] = fmax2(s, w2, acc[i][j]);
                }
        }
        __syncthreads();
    }

    const float b2v = b2[0];
    float ut[4], uo[4];
    #pragma unroll
    for (int i = 0; i < 4; ++i) ut[i] = g_u[t0 + ty * 4 + i];
    #pragma unroll
    for (int r = 0; r < 4; ++r) uo[r] = g_u[T_DIM + o0 + tx + 16 * r];

    #pragma unroll
    for (int i = 0; i < 4; ++i) {
        float* orow = out + (t0 + ty * 4 + i) * O_DIM + o0;
        #pragma unroll
        for (int r = 0; r < 4; ++r) {
            F2U cu; cu.u = acc[i][r];
            const float S = cu.f.x + cu.f.y;
            orow[tx + 16 * r] = 0.505f * (ut[i] + uo[r]) + 0.495f * S + b2v;
        }
    }
}

// ---------------------------------------------------------------------------
extern "C" void kernel_launch(void* const* d_in, const int* in_sizes, int n_in,
                              void* d_out, int out_size)
{
    const float* z_t = (const float*)d_in[0];   // [1024,256]
    const float* z_o = (const float*)d_in[1];   // [512,256]
    const float* W1  = (const float*)d_in[2];   // [512,512]
    const float* b1  = (const float*)d_in[3];   // [512]
    const float* W2  = (const float*)d_in[4];   // [512,1]
    const float* b2  = (const float*)d_in[5];   // [1]
    float* out = (float*)d_out;                 // [1024,512]

    (void)in_sizes; (void)n_in; (void)out_size;

    gemm_kernel<<<dim3(H_DIM / 64, M_DIM / 32), 128>>>(z_t, z_o, W1, b1);
    rowdot_kernel<<<M_DIM / 8, 256>>>(W2);
    cfm_main_kernel<<<dim3(O_DIM / 64, T_DIM / 32), 128>>>(W2, b2, out);
}